// round 2
// baseline (speedup 1.0000x reference)
#include <cuda_runtime.h>

#define T_  256
#define B_  64
#define H_  1024
#define G3  3072
#define I_  2048
#define TB  16384   // T_*B_

// ---------------- scratch (static device allocations: allowed) --------------
__device__ float g_gi[2][(size_t)TB * G3];     // input projections per direction (402 MB)
__device__ float g_buf[2][(size_t)TB * I_];    // inter-layer activations (256 MB)
__device__ float g_h[2][2][B_ * H_];           // [parity][dir][B*H] hidden state

// ---------------- helpers ---------------------------------------------------
__device__ __forceinline__ unsigned f2tf(float f) {
    unsigned u;
    asm("cvt.rna.tf32.f32 %0, %1;" : "=r"(u) : "f"(f));
    return u;
}

__device__ __forceinline__ void mma8(float* c, const unsigned* a, const unsigned* b) {
    asm volatile(
        "mma.sync.aligned.m16n8k8.row.col.f32.tf32.tf32.f32 "
        "{%0,%1,%2,%3}, {%4,%5,%6,%7}, {%8,%9}, {%0,%1,%2,%3};"
        : "+f"(c[0]), "+f"(c[1]), "+f"(c[2]), "+f"(c[3])
        : "r"(a[0]), "r"(a[1]), "r"(a[2]), "r"(a[3]),
          "r"(b[0]), "r"(b[1]));
}

// ---------------- input projection GEMM -------------------------------------
// gi[d][m, n] = sum_k inp[m,k] * W_ih[l,d][n,k] + b_ih[l,d][n]
// m in [0,16384), n in [0,3072), K = 2048. Tile 128x64, BK=32, 256 threads.
__global__ __launch_bounds__(256) void gemm_gi_kernel(
    const float* __restrict__ x, const float* __restrict__ w_ih,
    const float* __restrict__ b_ih, int l)
{
    const int d = blockIdx.z;
    const float* A    = (l == 0) ? x : g_buf[l - 1];
    const float* W    = w_ih + (size_t)(l * 2 + d) * G3 * I_;
    const float* bias = b_ih + (l * 2 + d) * G3;
    float* C = g_gi[d];

    __shared__ unsigned As[128][33];
    __shared__ unsigned Bs[64][33];

    const int tid  = threadIdx.x;
    const int lane = tid & 31, warp = tid >> 5;
    const int wm = (warp & 3) * 32, wn = (warp >> 2) * 32;
    const int m0 = blockIdx.y * 128, n0 = blockIdx.x * 64;
    const int g8 = lane >> 2, tg = lane & 3;

    float acc[2][4][4];
    #pragma unroll
    for (int a = 0; a < 2; a++)
        #pragma unroll
        for (int b = 0; b < 4; b++)
            #pragma unroll
            for (int i = 0; i < 4; i++) acc[a][b][i] = 0.f;

    for (int kt = 0; kt < I_; kt += 32) {
        #pragma unroll
        for (int i = 0; i < 4; i++) {              // A tile 128x32
            int idx = tid + 256 * i;
            int row = idx >> 3, c4 = (idx & 7) * 4;
            float4 v = *reinterpret_cast<const float4*>(
                &A[(size_t)(m0 + row) * I_ + kt + c4]);
            As[row][c4]     = f2tf(v.x); As[row][c4 + 1] = f2tf(v.y);
            As[row][c4 + 2] = f2tf(v.z); As[row][c4 + 3] = f2tf(v.w);
        }
        #pragma unroll
        for (int i = 0; i < 2; i++) {              // B tile 64x32 (W rows)
            int idx = tid + 256 * i;
            int row = idx >> 3, c4 = (idx & 7) * 4;
            float4 v = *reinterpret_cast<const float4*>(
                &W[(size_t)(n0 + row) * I_ + kt + c4]);
            Bs[row][c4]     = f2tf(v.x); Bs[row][c4 + 1] = f2tf(v.y);
            Bs[row][c4 + 2] = f2tf(v.z); Bs[row][c4 + 3] = f2tf(v.w);
        }
        __syncthreads();
        #pragma unroll
        for (int kk = 0; kk < 32; kk += 8) {
            unsigned af[2][4], bf[4][2];
            #pragma unroll
            for (int mt = 0; mt < 2; mt++) {
                int rbm = wm + mt * 16;
                af[mt][0] = As[rbm + g8][kk + tg];
                af[mt][1] = As[rbm + g8 + 8][kk + tg];
                af[mt][2] = As[rbm + g8][kk + tg + 4];
                af[mt][3] = As[rbm + g8 + 8][kk + tg + 4];
            }
            #pragma unroll
            for (int nt = 0; nt < 4; nt++) {
                int nb = wn + nt * 8 + g8;
                bf[nt][0] = Bs[nb][kk + tg];
                bf[nt][1] = Bs[nb][kk + tg + 4];
            }
            #pragma unroll
            for (int mt = 0; mt < 2; mt++)
                #pragma unroll
                for (int nt = 0; nt < 4; nt++)
                    mma8(acc[mt][nt], af[mt], bf[nt]);
        }
        __syncthreads();
    }

    #pragma unroll
    for (int mt = 0; mt < 2; mt++)
        #pragma unroll
        for (int nt = 0; nt < 4; nt++)
            #pragma unroll
            for (int i = 0; i < 4; i++) {
                int row = m0 + wm + mt * 16 + g8 + 8 * (i >> 1);
                int col = n0 + wn + nt * 8 + 2 * tg + (i & 1);
                C[(size_t)row * G3 + col] = acc[mt][nt][i] + __ldg(&bias[col]);
            }
}

// ---------------- fused recurrent step --------------------------------------
// One CTA = (dir, 16-col j tile). Computes gh for all 3 gates of its j columns
// (M=64=B, N=48, K=1024), then gate math + h update + y write.
__global__ __launch_bounds__(128) void step_kernel(
    const float* __restrict__ w_hh, const float* __restrict__ b_hh,
    float* __restrict__ d_out, int l, int s)
{
    const int dir = blockIdx.y;
    const int j0  = blockIdx.x * 16;
    const int t   = dir ? (T_ - 1 - s) : s;
    const float* W   = w_hh + (size_t)(l * 2 + dir) * G3 * H_;
    const float* bh  = b_hh + (l * 2 + dir) * G3;
    const float* cur = g_h[s & 1][dir];
    float* nxt = g_h[(s + 1) & 1][dir];
    float* y   = (l == 2) ? d_out : g_buf[l];

    __shared__ unsigned Hs[64][65];   // h tile  [B=64][KC=64]
    __shared__ unsigned Ws[48][65];   // W tile  [3 gates x 16 j][KC=64]

    const int tid  = threadIdx.x;
    const int lane = tid & 31, warp = tid >> 5;
    const int rb = warp * 16;                 // M rows of this warp
    const int g8 = lane >> 2, tg = lane & 3;

    float acc[6][4];                           // tile tt = gate*2 + jhalf
    #pragma unroll
    for (int a = 0; a < 6; a++)
        #pragma unroll
        for (int i = 0; i < 4; i++) acc[a][i] = 0.f;

    for (int kt = 0; kt < H_; kt += 64) {
        #pragma unroll
        for (int i = 0; i < 8; i++) {          // h: 64x64
            int idx = tid + 128 * i;
            int row = idx >> 4, c4 = (idx & 15) * 4;
            float4 v = *reinterpret_cast<const float4*>(
                &cur[row * H_ + kt + c4]);
            Hs[row][c4]     = f2tf(v.x); Hs[row][c4 + 1] = f2tf(v.y);
            Hs[row][c4 + 2] = f2tf(v.z); Hs[row][c4 + 3] = f2tf(v.w);
        }
        #pragma unroll
        for (int i = 0; i < 6; i++) {          // W: 48x64
            int idx = tid + 128 * i;
            int row = idx >> 4, c4 = (idx & 15) * 4;
            int g = row >> 4, jj = row & 15;
            float4 v = *reinterpret_cast<const float4*>(
                &W[(size_t)(g * H_ + j0 + jj) * H_ + kt + c4]);
            Ws[row][c4]     = f2tf(v.x); Ws[row][c4 + 1] = f2tf(v.y);
            Ws[row][c4 + 2] = f2tf(v.z); Ws[row][c4 + 3] = f2tf(v.w);
        }
        __syncthreads();
        #pragma unroll
        for (int kk = 0; kk < 64; kk += 8) {
            unsigned af[4];
            af[0] = Hs[rb + g8][kk + tg];
            af[1] = Hs[rb + g8 + 8][kk + tg];
            af[2] = Hs[rb + g8][kk + tg + 4];
            af[3] = Hs[rb + g8 + 8][kk + tg + 4];
            #pragma unroll
            for (int tt = 0; tt < 6; tt++) {
                unsigned bf[2];
                bf[0] = Ws[tt * 8 + g8][kk + tg];
                bf[1] = Ws[tt * 8 + g8][kk + tg + 4];
                mma8(acc[tt], af, bf);
            }
        }
        __syncthreads();
    }

    // gate math (r,z,n), h update, y write
    #pragma unroll
    for (int jh = 0; jh < 2; jh++)
        #pragma unroll
        for (int i = 0; i < 4; i++) {
            int b = rb + g8 + 8 * (i >> 1);
            int j = j0 + jh * 8 + 2 * tg + (i & 1);
            const float* gi = g_gi[dir] + (size_t)(t * B_ + b) * G3;
            float r = 1.f / (1.f + expf(-(gi[j]           + acc[0 + jh][i] + bh[j])));
            float z = 1.f / (1.f + expf(-(gi[H_ + j]      + acc[2 + jh][i] + bh[H_ + j])));
            float n = tanhf(gi[2 * H_ + j] + r * (acc[4 + jh][i] + bh[2 * H_ + j]));
            float hp = cur[b * H_ + j];
            float hn = (1.f - z) * n + z * hp;
            nxt[b * H_ + j] = hn;
            y[(size_t)(t * B_ + b) * 2048 + dir * H_ + j] = hn;
        }
}

// ---------------- h0 init ----------------------------------------------------
__global__ void init_h_kernel(const float* __restrict__ h0, int l)
{
    int i = blockIdx.x * blockDim.x + threadIdx.x;
    if (i < 2 * B_ * H_) {
        // i = dir*65536 + b*1024 + j  matches h0[2l+dir, b, j] contiguous layout
        g_h[0][i >> 16][i & 0xFFFF] = h0[(size_t)(2 * l) * B_ * H_ + i];
    }
}

// ---------------- launch ------------------------------------------------------
extern "C" void kernel_launch(void* const* d_in, const int* in_sizes, int n_in,
                              void* d_out, int out_size)
{
    const float* x    = (const float*)d_in[0];
    const float* h0   = (const float*)d_in[1];
    const float* w_ih = (const float*)d_in[2];
    const float* w_hh = (const float*)d_in[3];
    const float* b_ih = (const float*)d_in[4];
    const float* b_hh = (const float*)d_in[5];
    float* out = (float*)d_out;

    for (int l = 0; l < 3; l++) {
        dim3 gg(G3 / 64, TB / 128, 2);            // 48 x 128 x 2 CTAs
        gemm_gi_kernel<<<gg, 256>>>(x, w_ih, b_ih, l);
        init_h_kernel<<<(2 * B_ * H_ + 255) / 256, 256>>>(h0, l);
        for (int s = 0; s < T_; s++) {
            step_kernel<<<dim3(64, 2), 128>>>(w_hh, b_hh, out, l, s);
        }
    }
}

// round 4
// speedup vs baseline: 1.7160x; 1.7160x over previous
#include <cuda_runtime.h>

#define T_  256
#define B_  64
#define H_  1024
#define G3  3072
#define I_  2048
#define TB  16384   // T_*B_

#define WS_STRIDE 1028          // 48 x 1028 words  (mod 32 == 4 -> conflict-free)
#define HS_STRIDE 132           // 64 x 132 words
#define SMEM_STEP ((48 * WS_STRIDE + 64 * HS_STRIDE) * 4)   // 231,168 B

// ---------------- scratch (static device allocations: allowed) --------------
__device__ float g_gi[2][(size_t)TB * G3];     // input projections per direction
__device__ float g_buf[2][(size_t)TB * I_];    // inter-layer activations
__device__ float g_h[2][2][B_ * H_];           // [parity][dir][B*H] hidden state
__device__ unsigned g_bar[2];                  // per-direction step barrier

// ---------------- helpers ---------------------------------------------------
__device__ __forceinline__ unsigned f2tf(float f) {
    unsigned u;
    asm("cvt.rna.tf32.f32 %0, %1;" : "=r"(u) : "f"(f));
    return u;
}

__device__ __forceinline__ void mma8(float* c, const unsigned* a, const unsigned* b) {
    asm volatile(
        "mma.sync.aligned.m16n8k8.row.col.f32.tf32.tf32.f32 "
        "{%0,%1,%2,%3}, {%4,%5,%6,%7}, {%8,%9}, {%0,%1,%2,%3};"
        : "+f"(c[0]), "+f"(c[1]), "+f"(c[2]), "+f"(c[3])
        : "r"(a[0]), "r"(a[1]), "r"(a[2]), "r"(a[3]),
          "r"(b[0]), "r"(b[1]));
}

// ---------------- input projection GEMM -------------------------------------
__global__ __launch_bounds__(256) void gemm_gi_kernel(
    const float* __restrict__ x, const float* __restrict__ w_ih,
    const float* __restrict__ b_ih, int l)
{
    const int d = blockIdx.z;
    const float* A    = (l == 0) ? x : g_buf[l - 1];
    const float* W    = w_ih + (size_t)(l * 2 + d) * G3 * I_;
    const float* bias = b_ih + (l * 2 + d) * G3;
    float* C = g_gi[d];

    __shared__ unsigned As[128][33];
    __shared__ unsigned Bs[64][33];

    const int tid  = threadIdx.x;
    const int lane = tid & 31, warp = tid >> 5;
    const int wm = (warp & 3) * 32, wn = (warp >> 2) * 32;
    const int m0 = blockIdx.y * 128, n0 = blockIdx.x * 64;
    const int g8 = lane >> 2, tg = lane & 3;

    float acc[2][4][4];
    #pragma unroll
    for (int a = 0; a < 2; a++)
        #pragma unroll
        for (int b = 0; b < 4; b++)
            #pragma unroll
            for (int i = 0; i < 4; i++) acc[a][b][i] = 0.f;

    for (int kt = 0; kt < I_; kt += 32) {
        #pragma unroll
        for (int i = 0; i < 4; i++) {
            int idx = tid + 256 * i;
            int row = idx >> 3, c4 = (idx & 7) * 4;
            float4 v = *reinterpret_cast<const float4*>(
                &A[(size_t)(m0 + row) * I_ + kt + c4]);
            As[row][c4]     = f2tf(v.x); As[row][c4 + 1] = f2tf(v.y);
            As[row][c4 + 2] = f2tf(v.z); As[row][c4 + 3] = f2tf(v.w);
        }
        #pragma unroll
        for (int i = 0; i < 2; i++) {
            int idx = tid + 256 * i;
            int row = idx >> 3, c4 = (idx & 7) * 4;
            float4 v = *reinterpret_cast<const float4*>(
                &W[(size_t)(n0 + row) * I_ + kt + c4]);
            Bs[row][c4]     = f2tf(v.x); Bs[row][c4 + 1] = f2tf(v.y);
            Bs[row][c4 + 2] = f2tf(v.z); Bs[row][c4 + 3] = f2tf(v.w);
        }
        __syncthreads();
        #pragma unroll
        for (int kk = 0; kk < 32; kk += 8) {
            unsigned af[2][4], bf[4][2];
            #pragma unroll
            for (int mt = 0; mt < 2; mt++) {
                int rbm = wm + mt * 16;
                af[mt][0] = As[rbm + g8][kk + tg];
                af[mt][1] = As[rbm + g8 + 8][kk + tg];
                af[mt][2] = As[rbm + g8][kk + tg + 4];
                af[mt][3] = As[rbm + g8 + 8][kk + tg + 4];
            }
            #pragma unroll
            for (int nt = 0; nt < 4; nt++) {
                int nb = wn + nt * 8 + g8;
                bf[nt][0] = Bs[nb][kk + tg];
                bf[nt][1] = Bs[nb][kk + tg + 4];
            }
            #pragma unroll
            for (int mt = 0; mt < 2; mt++)
                #pragma unroll
                for (int nt = 0; nt < 4; nt++)
                    mma8(acc[mt][nt], af[mt], bf[nt]);
        }
        __syncthreads();
    }

    #pragma unroll
    for (int mt = 0; mt < 2; mt++)
        #pragma unroll
        for (int nt = 0; nt < 4; nt++)
            #pragma unroll
            for (int i = 0; i < 4; i++) {
                int row = m0 + wm + mt * 16 + g8 + 8 * (i >> 1);
                int col = n0 + wn + nt * 8 + 2 * tg + (i & 1);
                C[(size_t)row * G3 + col] = acc[mt][nt][i] + __ldg(&bias[col]);
            }
}

// ---------------- h0 init & barrier reset -----------------------------------
__global__ void init_h_kernel(const float* __restrict__ h0, int l)
{
    int i = blockIdx.x * blockDim.x + threadIdx.x;
    if (i < 2 * B_ * H_) {
        g_h[0][i >> 16][i & 0xFFFF] = h0[(size_t)(2 * l) * B_ * H_ + i];
    }
    if (i < 2) g_bar[i] = 0;
}

// ---------------- persistent recurrent kernel -------------------------------
// 128 CTAs (1/SM via 231KB smem), 256 threads. CTA = (dir, 16-col j tile).
// W_hh slice (48 x 1024 tf32, 192KB) stays in SMEM for all 256 steps.
extern __shared__ unsigned smem_dyn[];

__global__ __launch_bounds__(256, 1) void gru_persistent_kernel(
    const float* __restrict__ w_hh, const float* __restrict__ b_hh,
    float* __restrict__ d_out, int l)
{
    const int cta = blockIdx.x;
    const int dir = cta >> 6;
    const int j0  = (cta & 63) * 16;
    const float* W  = w_hh + (size_t)(l * 2 + dir) * G3 * H_;
    const float* bh = b_hh + (l * 2 + dir) * G3;
    float* y = (l == 2) ? d_out : g_buf[l];

    unsigned* Ws = smem_dyn;                  // [48][WS_STRIDE]
    unsigned* Hs = smem_dyn + 48 * WS_STRIDE; // [64][HS_STRIDE]

    const int tid  = threadIdx.x;
    const int lane = tid & 31, warp = tid >> 5;
    const int rb = (warp & 3) * 16;           // B rows of this warp
    const int jh = warp >> 2;                 // j half (0,1)
    const int gq = lane >> 2, tg = lane & 3;

    // ---- load W slice once per layer: local row = gate*16 + jj ----
    #pragma unroll 4
    for (int i = 0; i < 48; i++) {
        int idx = tid + 256 * i;
        int row = idx >> 8;                 // 0..47
        int c4  = (idx & 255) * 4;
        int g = row >> 4, jj = row & 15;
        float4 v = *reinterpret_cast<const float4*>(
            &W[(size_t)(g * H_ + j0 + jj) * H_ + c4]);
        unsigned* w = &Ws[row * WS_STRIDE + c4];
        w[0] = f2tf(v.x); w[1] = f2tf(v.y); w[2] = f2tf(v.z); w[3] = f2tf(v.w);
    }
    __syncthreads();

    for (int s = 0; s < T_; s++) {
        const int t = dir ? (T_ - 1 - s) : s;
        const float* cur = g_h[s & 1][dir];
        float* nxt = g_h[(s + 1) & 1][dir];

        float acc[3][4];
        #pragma unroll
        for (int g = 0; g < 3; g++)
            #pragma unroll
            for (int i = 0; i < 4; i++) acc[g][i] = 0.f;

        // prefetch h chunk 0 (64 rows x 128 cols)
        float4 R[8];
        #pragma unroll
        for (int i = 0; i < 8; i++) {
            int idx = tid + 256 * i;
            int row = idx >> 5, c4 = (idx & 31) * 4;
            R[i] = __ldcg(reinterpret_cast<const float4*>(&cur[row * H_ + c4]));
        }

        for (int c = 0; c < 8; c++) {
            __syncthreads();                 // prior chunk's mma done reading Hs
            #pragma unroll
            for (int i = 0; i < 8; i++) {
                int idx = tid + 256 * i;
                int row = idx >> 5, c4 = (idx & 31) * 4;
                unsigned* hh = &Hs[row * HS_STRIDE + c4];
                hh[0] = f2tf(R[i].x); hh[1] = f2tf(R[i].y);
                hh[2] = f2tf(R[i].z); hh[3] = f2tf(R[i].w);
            }
            if (c < 7) {                     // prefetch next chunk (overlaps mma)
                int kt = (c + 1) * 128;
                #pragma unroll
                for (int i = 0; i < 8; i++) {
                    int idx = tid + 256 * i;
                    int row = idx >> 5, c4 = (idx & 31) * 4;
                    R[i] = __ldcg(reinterpret_cast<const float4*>(
                        &cur[row * H_ + kt + c4]));
                }
            }
            __syncthreads();
            const int ktw = c * 128;
            #pragma unroll
            for (int kk = 0; kk < 128; kk += 8) {
                unsigned af[4];
                af[0] = Hs[(rb + gq) * HS_STRIDE + kk + tg];
                af[1] = Hs[(rb + gq + 8) * HS_STRIDE + kk + tg];
                af[2] = Hs[(rb + gq) * HS_STRIDE + kk + tg + 4];
                af[3] = Hs[(rb + gq + 8) * HS_STRIDE + kk + tg + 4];
                #pragma unroll
                for (int g = 0; g < 3; g++) {
                    const int wr = g * 16 + jh * 8 + gq;
                    unsigned bf[2];
                    bf[0] = Ws[wr * WS_STRIDE + ktw + kk + tg];
                    bf[1] = Ws[wr * WS_STRIDE + ktw + kk + tg + 4];
                    mma8(acc[g], af, bf);
                }
            }
        }

        // ---- gate math (r,z,n), h update, y write ----
        #pragma unroll
        for (int i = 0; i < 4; i++) {
            int b = rb + gq + 8 * (i >> 1);
            int j = j0 + jh * 8 + 2 * tg + (i & 1);
            const float* gi = g_gi[dir] + (size_t)(t * B_ + b) * G3;
            float r = 1.f / (1.f + expf(-(gi[j]          + acc[0][i] + bh[j])));
            float z = 1.f / (1.f + expf(-(gi[H_ + j]     + acc[1][i] + bh[H_ + j])));
            float n = tanhf(gi[2 * H_ + j] + r * (acc[2][i] + bh[2 * H_ + j]));
            float hp = __ldcg(&cur[b * H_ + j]);
            float hn = (1.f - z) * n + z * hp;
            __stcg(&nxt[b * H_ + j], hn);
            y[(size_t)(t * B_ + b) * 2048 + dir * H_ + j] = hn;
        }

        // ---- per-direction grid barrier ----
        __threadfence();
        __syncthreads();
        if (tid == 0) {
            atomicAdd(&g_bar[dir], 1u);
            const unsigned target = 64u * (unsigned)(s + 1);
            while (*((volatile unsigned*)&g_bar[dir]) < target) {
                __nanosleep(64);
            }
        }
        __syncthreads();
        __threadfence();
    }
}

// ---------------- launch ------------------------------------------------------
extern "C" void kernel_launch(void* const* d_in, const int* in_sizes, int n_in,
                              void* d_out, int out_size)
{
    const float* x    = (const float*)d_in[0];
    const float* h0   = (const float*)d_in[1];
    const float* w_ih = (const float*)d_in[2];
    const float* w_hh = (const float*)d_in[3];
    const float* b_ih = (const float*)d_in[4];
    const float* b_hh = (const float*)d_in[5];
    float* out = (float*)d_out;

    // Unconditional (no static guards per harness rules); idempotent, not a
    // stream op, graph-capture safe.
    cudaFuncSetAttribute(gru_persistent_kernel,
                         cudaFuncAttributeMaxDynamicSharedMemorySize,
                         SMEM_STEP);

    for (int l = 0; l < 3; l++) {
        dim3 gg(G3 / 64, TB / 128, 2);
        gemm_gi_kernel<<<gg, 256>>>(x, w_ih, b_ih, l);
        init_h_kernel<<<(2 * B_ * H_ + 255) / 256, 256>>>(h0, l);
        gru_persistent_kernel<<<128, 256, SMEM_STEP>>>(w_hh, b_hh, out, l);
    }
}

// round 5
// speedup vs baseline: 1.7654x; 1.0288x over previous
#include <cuda_runtime.h>

#define T_  256
#define B_  64
#define H_  1024
#define G3  3072
#define I_  2048
#define TB  16384   // T_*B_

// smem layout (words): Ws[48*1024] XOR-swizzled | Hs[2 buffers][64 rows][68]
#define WS_WORDS   (48 * 1024)
#define HS_STRIDE  68
#define HS_BUFW    (64 * HS_STRIDE)           // 4352 words = 17408 B
#define SMEM_STEP  ((WS_WORDS + 2 * HS_BUFW) * 4)   // 231,424 B

// ---------------- scratch (static device allocations: allowed) --------------
__device__ float g_gi[2][(size_t)TB * G3];     // input projections per direction
__device__ float g_buf[2][(size_t)TB * I_];    // inter-layer activations
__device__ float g_h[2][2][B_ * H_];           // [parity][dir][B*H] hidden state
__device__ unsigned g_bar[2];                  // per-direction step barrier

// ---------------- helpers ---------------------------------------------------
__device__ __forceinline__ unsigned f2tf(float f) {
    unsigned u;
    asm("cvt.rna.tf32.f32 %0, %1;" : "=r"(u) : "f"(f));
    return u;
}

__device__ __forceinline__ void mma8(float* c, const unsigned* a, const unsigned* b) {
    asm volatile(
        "mma.sync.aligned.m16n8k8.row.col.f32.tf32.tf32.f32 "
        "{%0,%1,%2,%3}, {%4,%5,%6,%7}, {%8,%9}, {%0,%1,%2,%3};"
        : "+f"(c[0]), "+f"(c[1]), "+f"(c[2]), "+f"(c[3])
        : "r"(a[0]), "r"(a[1]), "r"(a[2]), "r"(a[3]),
          "r"(b[0]), "r"(b[1]));
}

// ---------------- input projection GEMM (unchanged) -------------------------
__global__ __launch_bounds__(256) void gemm_gi_kernel(
    const float* __restrict__ x, const float* __restrict__ w_ih,
    const float* __restrict__ b_ih, int l)
{
    const int d = blockIdx.z;
    const float* A    = (l == 0) ? x : g_buf[l - 1];
    const float* W    = w_ih + (size_t)(l * 2 + d) * G3 * I_;
    const float* bias = b_ih + (l * 2 + d) * G3;
    float* C = g_gi[d];

    __shared__ unsigned As[128][33];
    __shared__ unsigned Bs[64][33];

    const int tid  = threadIdx.x;
    const int lane = tid & 31, warp = tid >> 5;
    const int wm = (warp & 3) * 32, wn = (warp >> 2) * 32;
    const int m0 = blockIdx.y * 128, n0 = blockIdx.x * 64;
    const int g8 = lane >> 2, tg = lane & 3;

    float acc[2][4][4];
    #pragma unroll
    for (int a = 0; a < 2; a++)
        #pragma unroll
        for (int b = 0; b < 4; b++)
            #pragma unroll
            for (int i = 0; i < 4; i++) acc[a][b][i] = 0.f;

    for (int kt = 0; kt < I_; kt += 32) {
        #pragma unroll
        for (int i = 0; i < 4; i++) {
            int idx = tid + 256 * i;
            int row = idx >> 3, c4 = (idx & 7) * 4;
            float4 v = *reinterpret_cast<const float4*>(
                &A[(size_t)(m0 + row) * I_ + kt + c4]);
            As[row][c4]     = f2tf(v.x); As[row][c4 + 1] = f2tf(v.y);
            As[row][c4 + 2] = f2tf(v.z); As[row][c4 + 3] = f2tf(v.w);
        }
        #pragma unroll
        for (int i = 0; i < 2; i++) {
            int idx = tid + 256 * i;
            int row = idx >> 3, c4 = (idx & 7) * 4;
            float4 v = *reinterpret_cast<const float4*>(
                &W[(size_t)(n0 + row) * I_ + kt + c4]);
            Bs[row][c4]     = f2tf(v.x); Bs[row][c4 + 1] = f2tf(v.y);
            Bs[row][c4 + 2] = f2tf(v.z); Bs[row][c4 + 3] = f2tf(v.w);
        }
        __syncthreads();
        #pragma unroll
        for (int kk = 0; kk < 32; kk += 8) {
            unsigned af[2][4], bf[4][2];
            #pragma unroll
            for (int mt = 0; mt < 2; mt++) {
                int rbm = wm + mt * 16;
                af[mt][0] = As[rbm + g8][kk + tg];
                af[mt][1] = As[rbm + g8 + 8][kk + tg];
                af[mt][2] = As[rbm + g8][kk + tg + 4];
                af[mt][3] = As[rbm + g8 + 8][kk + tg + 4];
            }
            #pragma unroll
            for (int nt = 0; nt < 4; nt++) {
                int nb = wn + nt * 8 + g8;
                bf[nt][0] = Bs[nb][kk + tg];
                bf[nt][1] = Bs[nb][kk + tg + 4];
            }
            #pragma unroll
            for (int mt = 0; mt < 2; mt++)
                #pragma unroll
                for (int nt = 0; nt < 4; nt++)
                    mma8(acc[mt][nt], af[mt], bf[nt]);
        }
        __syncthreads();
    }

    #pragma unroll
    for (int mt = 0; mt < 2; mt++)
        #pragma unroll
        for (int nt = 0; nt < 4; nt++)
            #pragma unroll
            for (int i = 0; i < 4; i++) {
                int row = m0 + wm + mt * 16 + g8 + 8 * (i >> 1);
                int col = n0 + wn + nt * 8 + 2 * tg + (i & 1);
                C[(size_t)row * G3 + col] = acc[mt][nt][i] + __ldg(&bias[col]);
            }
}

// ---------------- h0 init & barrier reset -----------------------------------
__global__ void init_h_kernel(const float* __restrict__ h0, int l)
{
    int i = blockIdx.x * blockDim.x + threadIdx.x;
    if (i < 2 * B_ * H_) {
        g_h[0][i >> 16][i & 0xFFFF] = h0[(size_t)(2 * l) * B_ * H_ + i];
    }
    if (i < 2) g_bar[i] = 0;
}

// ---------------- persistent recurrent kernel -------------------------------
// 128 CTAs (1/SM via 231KB smem), 256 threads. CTA = (dir, 16-col j tile).
// W_hh slice (48x1024 tf32, XOR-swizzled, 192KB) in SMEM all 256 steps.
// H streamed per step via cp.async into 2x(64x64) double buffer (raw f32,
// cvt to tf32 in-register at mma feed -> numerics identical to R4).
extern __shared__ unsigned smem_dyn[];

__global__ __launch_bounds__(256, 1) void gru_persistent_kernel(
    const float* __restrict__ w_hh, const float* __restrict__ b_hh,
    float* __restrict__ d_out, int l)
{
    const int cta = blockIdx.x;
    const int dir = cta >> 6;
    const int j0  = (cta & 63) * 16;
    const float* W  = w_hh + (size_t)(l * 2 + dir) * G3 * H_;
    const float* bh = b_hh + (l * 2 + dir) * G3;
    float* y = (l == 2) ? d_out : g_buf[l];

    unsigned* Ws = smem_dyn;                        // 48*1024 words, swizzled
    float* Hs = reinterpret_cast<float*>(smem_dyn + WS_WORDS);

    const int tid  = threadIdx.x;
    const int lane = tid & 31, warp = tid >> 5;
    const int rb = (warp & 3) * 16;                 // B rows of this warp
    const int jh = warp >> 2;                       // j half (0,1)
    const int gq = lane >> 2, tg = lane & 3;
    const unsigned swz = (unsigned)(gq << 2);       // W col XOR per lane

    // ---- load W slice once (swizzled: word = row*1024 + (col ^ ((row&7)<<2)))
    #pragma unroll 4
    for (int i = 0; i < 48; i++) {
        int idx = tid + 256 * i;
        int row = idx >> 8;                 // 0..47
        int c4  = (idx & 255) * 4;
        int g = row >> 4, jj = row & 15;
        float4 v = *reinterpret_cast<const float4*>(
            &W[(size_t)(g * H_ + j0 + jj) * H_ + c4]);
        unsigned* w = &Ws[row * 1024 + (c4 ^ ((row & 7) << 2))];
        w[0] = f2tf(v.x); w[1] = f2tf(v.y); w[2] = f2tf(v.z); w[3] = f2tf(v.w);
    }

    // ---- hoist bias (per-thread 3 gates x 2 j) ----
    const int jA = j0 + jh * 8 + 2 * tg;
    float bhv[3][2];
    #pragma unroll
    for (int g = 0; g < 3; g++) {
        bhv[g][0] = __ldg(&bh[g * H_ + jA]);
        bhv[g][1] = __ldg(&bh[g * H_ + jA + 1]);
    }

    // producer mapping: thread t copies 4x16B of row prow, granules pg..pg+3
    unsigned hs_u32 = (unsigned)__cvta_generic_to_shared(Hs);
    const int prow = tid >> 2;
    const int pg   = (tid & 3) * 4;

    __syncthreads();

    for (int s = 0; s < T_; s++) {
        const int t = dir ? (T_ - 1 - s) : s;
        const float* cur = g_h[s & 1][dir];
        float* nxt = g_h[(s + 1) & 1][dir];

        // ---- issue chunks 0 and 1 immediately ----
        #pragma unroll
        for (int c = 0; c < 2; c++) {
            unsigned dst = hs_u32 + c * (HS_BUFW * 4) + prow * (HS_STRIDE * 4);
            const float* src = cur + prow * H_ + c * 64;
            #pragma unroll
            for (int i = 0; i < 4; i++) {
                asm volatile("cp.async.cg.shared.global [%0], [%1], 16;\n"
                             :: "r"(dst + (pg + i) * 16), "l"(src + (pg + i) * 4));
            }
            asm volatile("cp.async.commit_group;\n");
        }

        // ---- prefetch gi / h_prev (latency overlaps whole GEMM) ----
        float giv[3][4], hpv[4];
        #pragma unroll
        for (int i = 0; i < 4; i++) {
            int b = rb + gq + 8 * (i >> 1);
            int j = jA + (i & 1);
            const float* gi = g_gi[dir] + (size_t)(t * B_ + b) * G3;
            giv[0][i] = __ldg(&gi[j]);
            giv[1][i] = __ldg(&gi[H_ + j]);
            giv[2][i] = __ldg(&gi[2 * H_ + j]);
            hpv[i] = __ldcg(&cur[b * H_ + j]);
        }

        float acc[3][4];
        #pragma unroll
        for (int g = 0; g < 3; g++)
            #pragma unroll
            for (int i = 0; i < 4; i++) acc[g][i] = 0.f;

        for (int c = 0; c < 16; c++) {
            if (c == 15) asm volatile("cp.async.wait_group 0;\n" ::: "memory");
            else         asm volatile("cp.async.wait_group 1;\n" ::: "memory");
            __syncthreads();                 // chunk c visible to all warps

            const float* hb = Hs + (c & 1) * HS_BUFW;
            const int kbase = c * 64;
            #pragma unroll
            for (int kk = 0; kk < 64; kk += 8) {
                float a0 = hb[(rb + gq) * HS_STRIDE + kk + tg];
                float a1 = hb[(rb + gq + 8) * HS_STRIDE + kk + tg];
                float a2 = hb[(rb + gq) * HS_STRIDE + kk + tg + 4];
                float a3 = hb[(rb + gq + 8) * HS_STRIDE + kk + tg + 4];
                unsigned af[4] = {f2tf(a0), f2tf(a1), f2tf(a2), f2tf(a3)};
                #pragma unroll
                for (int g = 0; g < 3; g++) {
                    const int wr = g * 16 + jh * 8 + gq;
                    unsigned bf[2];
                    bf[0] = Ws[wr * 1024 + ((unsigned)(kbase + kk + tg) ^ swz)];
                    bf[1] = Ws[wr * 1024 + ((unsigned)(kbase + kk + tg + 4) ^ swz)];
                    mma8(acc[g], af, bf);
                }
            }
            __syncthreads();                 // mma on buf (c&1) done by all

            if (c < 14) {                    // refill buf (c&1) with chunk c+2
                unsigned dst = hs_u32 + (c & 1) * (HS_BUFW * 4)
                             + prow * (HS_STRIDE * 4);
                const float* src = cur + prow * H_ + (c + 2) * 64;
                #pragma unroll
                for (int i = 0; i < 4; i++) {
                    asm volatile("cp.async.cg.shared.global [%0], [%1], 16;\n"
                                 :: "r"(dst + (pg + i) * 16), "l"(src + (pg + i) * 4));
                }
                asm volatile("cp.async.commit_group;\n");
            }
        }

        // ---- gate math (r,z,n), h update, y write ----
        #pragma unroll
        for (int i = 0; i < 4; i++) {
            int b = rb + gq + 8 * (i >> 1);
            int j = jA + (i & 1);
            float r = 1.f / (1.f + expf(-(giv[0][i] + acc[0][i] + bhv[0][i & 1])));
            float z = 1.f / (1.f + expf(-(giv[1][i] + acc[1][i] + bhv[1][i & 1])));
            float n = tanhf(giv[2][i] + r * (acc[2][i] + bhv[2][i & 1]));
            float hn = (1.f - z) * n + z * hpv[i];
            __stcg(&nxt[b * H_ + j], hn);
            y[(size_t)(t * B_ + b) * 2048 + dir * H_ + j] = hn;
        }

        // ---- per-direction grid barrier (release by fence+atomic) ----
        __threadfence();
        __syncthreads();
        if (tid == 0) {
            atomicAdd(&g_bar[dir], 1u);
            const unsigned target = 64u * (unsigned)(s + 1);
            while (*((volatile unsigned*)&g_bar[dir]) < target) {
                __nanosleep(32);
            }
        }
        __syncthreads();
    }
}

// ---------------- launch ------------------------------------------------------
extern "C" void kernel_launch(void* const* d_in, const int* in_sizes, int n_in,
                              void* d_out, int out_size)
{
    const float* x    = (const float*)d_in[0];
    const float* h0   = (const float*)d_in[1];
    const float* w_ih = (const float*)d_in[2];
    const float* w_hh = (const float*)d_in[3];
    const float* b_ih = (const float*)d_in[4];
    const float* b_hh = (const float*)d_in[5];
    float* out = (float*)d_out;

    cudaFuncSetAttribute(gru_persistent_kernel,
                         cudaFuncAttributeMaxDynamicSharedMemorySize,
                         SMEM_STEP);

    for (int l = 0; l < 3; l++) {
        dim3 gg(G3 / 64, TB / 128, 2);
        gemm_gi_kernel<<<gg, 256>>>(x, w_ih, b_ih, l);
        init_h_kernel<<<(2 * B_ * H_ + 255) / 256, 256>>>(h0, l);
        gru_persistent_kernel<<<128, 256, SMEM_STEP>>>(w_hh, b_hh, out, l);
    }
}

// round 6
// speedup vs baseline: 1.8871x; 1.0690x over previous
#include <cuda_runtime.h>

#define T_  256
#define B_  64
#define H_  1024
#define G3  3072
#define I_  2048
#define TB  16384   // T_*B_

// smem layout (words): Ws[48*1024] XOR-swizzled | Hs[2 buffers][64 rows][68]
#define WS_WORDS   (48 * 1024)
#define HS_STRIDE  68
#define HS_BUFW    (64 * HS_STRIDE)           // 4352 words = 17408 B
#define SMEM_STEP  ((WS_WORDS + 2 * HS_BUFW) * 4)   // 231,424 B

// ---------------- scratch (static device allocations: allowed) --------------
__device__ float g_gi[2][(size_t)TB * G3];     // input projections per direction
__device__ float g_buf[2][(size_t)TB * I_];    // inter-layer activations
__device__ float g_h[2][2][B_ * H_];           // [parity][dir][B*H] hidden state
__device__ unsigned g_bar[2];                  // per-direction step barrier

// ---------------- helpers ---------------------------------------------------
__device__ __forceinline__ unsigned f2tf(float f) {
    unsigned u;
    asm("cvt.rna.tf32.f32 %0, %1;" : "=r"(u) : "f"(f));
    return u;
}

__device__ __forceinline__ void mma8(float* c, const unsigned* a, const unsigned* b) {
    asm volatile(
        "mma.sync.aligned.m16n8k8.row.col.f32.tf32.tf32.f32 "
        "{%0,%1,%2,%3}, {%4,%5,%6,%7}, {%8,%9}, {%0,%1,%2,%3};"
        : "+f"(c[0]), "+f"(c[1]), "+f"(c[2]), "+f"(c[3])
        : "r"(a[0]), "r"(a[1]), "r"(a[2]), "r"(a[3]),
          "r"(b[0]), "r"(b[1]));
}

// ---------------- input projection GEMM (unchanged) -------------------------
__global__ __launch_bounds__(256) void gemm_gi_kernel(
    const float* __restrict__ x, const float* __restrict__ w_ih,
    const float* __restrict__ b_ih, int l)
{
    const int d = blockIdx.z;
    const float* A    = (l == 0) ? x : g_buf[l - 1];
    const float* W    = w_ih + (size_t)(l * 2 + d) * G3 * I_;
    const float* bias = b_ih + (l * 2 + d) * G3;
    float* C = g_gi[d];

    __shared__ unsigned As[128][33];
    __shared__ unsigned Bs[64][33];

    const int tid  = threadIdx.x;
    const int lane = tid & 31, warp = tid >> 5;
    const int wm = (warp & 3) * 32, wn = (warp >> 2) * 32;
    const int m0 = blockIdx.y * 128, n0 = blockIdx.x * 64;
    const int g8 = lane >> 2, tg = lane & 3;

    float acc[2][4][4];
    #pragma unroll
    for (int a = 0; a < 2; a++)
        #pragma unroll
        for (int b = 0; b < 4; b++)
            #pragma unroll
            for (int i = 0; i < 4; i++) acc[a][b][i] = 0.f;

    for (int kt = 0; kt < I_; kt += 32) {
        #pragma unroll
        for (int i = 0; i < 4; i++) {
            int idx = tid + 256 * i;
            int row = idx >> 3, c4 = (idx & 7) * 4;
            float4 v = *reinterpret_cast<const float4*>(
                &A[(size_t)(m0 + row) * I_ + kt + c4]);
            As[row][c4]     = f2tf(v.x); As[row][c4 + 1] = f2tf(v.y);
            As[row][c4 + 2] = f2tf(v.z); As[row][c4 + 3] = f2tf(v.w);
        }
        #pragma unroll
        for (int i = 0; i < 2; i++) {
            int idx = tid + 256 * i;
            int row = idx >> 3, c4 = (idx & 7) * 4;
            float4 v = *reinterpret_cast<const float4*>(
                &W[(size_t)(n0 + row) * I_ + kt + c4]);
            Bs[row][c4]     = f2tf(v.x); Bs[row][c4 + 1] = f2tf(v.y);
            Bs[row][c4 + 2] = f2tf(v.z); Bs[row][c4 + 3] = f2tf(v.w);
        }
        __syncthreads();
        #pragma unroll
        for (int kk = 0; kk < 32; kk += 8) {
            unsigned af[2][4], bf[4][2];
            #pragma unroll
            for (int mt = 0; mt < 2; mt++) {
                int rbm = wm + mt * 16;
                af[mt][0] = As[rbm + g8][kk + tg];
                af[mt][1] = As[rbm + g8 + 8][kk + tg];
                af[mt][2] = As[rbm + g8][kk + tg + 4];
                af[mt][3] = As[rbm + g8 + 8][kk + tg + 4];
            }
            #pragma unroll
            for (int nt = 0; nt < 4; nt++) {
                int nb = wn + nt * 8 + g8;
                bf[nt][0] = Bs[nb][kk + tg];
                bf[nt][1] = Bs[nb][kk + tg + 4];
            }
            #pragma unroll
            for (int mt = 0; mt < 2; mt++)
                #pragma unroll
                for (int nt = 0; nt < 4; nt++)
                    mma8(acc[mt][nt], af[mt], bf[nt]);
        }
        __syncthreads();
    }

    #pragma unroll
    for (int mt = 0; mt < 2; mt++)
        #pragma unroll
        for (int nt = 0; nt < 4; nt++)
            #pragma unroll
            for (int i = 0; i < 4; i++) {
                int row = m0 + wm + mt * 16 + g8 + 8 * (i >> 1);
                int col = n0 + wn + nt * 8 + 2 * tg + (i & 1);
                C[(size_t)row * G3 + col] = acc[mt][nt][i] + __ldg(&bias[col]);
            }
}

// ---------------- h0 init & barrier reset -----------------------------------
__global__ void init_h_kernel(const float* __restrict__ h0, int l)
{
    int i = blockIdx.x * blockDim.x + threadIdx.x;
    if (i < 2 * B_ * H_) {
        g_h[0][i >> 16][i & 0xFFFF] = h0[(size_t)(2 * l) * B_ * H_ + i];
    }
    if (i < 2) g_bar[i] = 0;
}

// ---------------- persistent recurrent kernel -------------------------------
// 128 CTAs (1/SM via 231KB smem), 512 threads / 16 warps. CTA = (dir, 16-col
// j tile). warp = (ks, jh, rb): ks = K-half split (kk 0-31 vs 32-63 of each
// chunk). W_hh slice (48x1024 tf32, swizzled, 192KB) resident all 256 steps.
extern __shared__ unsigned smem_dyn[];

__global__ __launch_bounds__(512, 1) void gru_persistent_kernel(
    const float* __restrict__ w_hh, const float* __restrict__ b_hh,
    float* __restrict__ d_out, int l)
{
    const int cta = blockIdx.x;
    const int dir = cta >> 6;
    const int j0  = (cta & 63) * 16;
    const float* W  = w_hh + (size_t)(l * 2 + dir) * G3 * H_;
    const float* bh = b_hh + (l * 2 + dir) * G3;
    float* y = (l == 2) ? d_out : g_buf[l];

    unsigned* Ws = smem_dyn;                        // 48*1024 words, swizzled
    float* Hs = reinterpret_cast<float*>(smem_dyn + WS_WORDS);

    const int tid  = threadIdx.x;
    const int lane = tid & 31, warp = tid >> 5;
    const int ks = warp >> 3;                       // K half (0,1)
    const int rb = (warp & 3) * 16;                 // B rows of this warp
    const int jh = (warp >> 2) & 1;                 // j half (0,1)
    const int gq = lane >> 2, tg = lane & 3;
    const unsigned swz = (unsigned)(gq << 2);       // W col XOR per lane
    const int kklo = ks * 32;

    // ---- load W slice once (swizzled: word = row*1024 + (col ^ ((row&7)<<2)))
    #pragma unroll 4
    for (int i = 0; i < 24; i++) {
        int idx = tid + 512 * i;
        int row = idx >> 8;                 // 0..47
        int c4  = (idx & 255) * 4;
        int g = row >> 4, jj = row & 15;
        float4 v = *reinterpret_cast<const float4*>(
            &W[(size_t)(g * H_ + j0 + jj) * H_ + c4]);
        unsigned* w = &Ws[row * 1024 + (c4 ^ ((row & 7) << 2))];
        w[0] = f2tf(v.x); w[1] = f2tf(v.y); w[2] = f2tf(v.z); w[3] = f2tf(v.w);
    }

    // ---- hoist bias (epilogue warps only) ----
    const int jA = j0 + jh * 8 + 2 * tg;
    float bhv[3][2];
    if (ks == 0) {
        #pragma unroll
        for (int g = 0; g < 3; g++) {
            bhv[g][0] = __ldg(&bh[g * H_ + jA]);
            bhv[g][1] = __ldg(&bh[g * H_ + jA + 1]);
        }
    }

    // producer mapping: thread copies 2x16B of row prow, granules pg, pg+1
    unsigned hs_u32 = (unsigned)__cvta_generic_to_shared(Hs);
    const int prow = tid >> 3;
    const int pg   = (tid & 7) * 2;

    __syncthreads();

    for (int s = 0; s < T_; s++) {
        const int t = dir ? (T_ - 1 - s) : s;
        const float* cur = g_h[s & 1][dir];
        float* nxt = g_h[(s + 1) & 1][dir];

        // ---- issue chunks 0 and 1 immediately ----
        #pragma unroll
        for (int c = 0; c < 2; c++) {
            unsigned dst = hs_u32 + c * (HS_BUFW * 4) + prow * (HS_STRIDE * 4);
            const float* src = cur + prow * H_ + c * 64;
            #pragma unroll
            for (int i = 0; i < 2; i++) {
                asm volatile("cp.async.cg.shared.global [%0], [%1], 16;\n"
                             :: "r"(dst + (pg + i) * 16), "l"(src + (pg + i) * 4));
            }
            asm volatile("cp.async.commit_group;\n");
        }

        // ---- prefetch gi / h_prev (epilogue warps; overlaps GEMM) ----
        float giv[3][4], hpv[4];
        if (ks == 0) {
            #pragma unroll
            for (int i = 0; i < 4; i++) {
                int b = rb + gq + 8 * (i >> 1);
                int j = jA + (i & 1);
                const float* gi = g_gi[dir] + (size_t)(t * B_ + b) * G3;
                giv[0][i] = __ldg(&gi[j]);
                giv[1][i] = __ldg(&gi[H_ + j]);
                giv[2][i] = __ldg(&gi[2 * H_ + j]);
                hpv[i] = __ldcg(&cur[b * H_ + j]);
            }
        }

        float acc[3][4];
        #pragma unroll
        for (int g = 0; g < 3; g++)
            #pragma unroll
            for (int i = 0; i < 4; i++) acc[g][i] = 0.f;

        for (int c = 0; c < 16; c++) {
            if (c == 15) asm volatile("cp.async.wait_group 0;\n" ::: "memory");
            else         asm volatile("cp.async.wait_group 1;\n" ::: "memory");
            __syncthreads();                 // chunk c visible to all warps

            const float* hb = Hs + (c & 1) * HS_BUFW;
            const int kb = c * 64 + kklo;    // this warp's global k base in W
            #pragma unroll
            for (int kk = 0; kk < 32; kk += 8) {
                float a0 = hb[(rb + gq) * HS_STRIDE + kklo + kk + tg];
                float a1 = hb[(rb + gq + 8) * HS_STRIDE + kklo + kk + tg];
                float a2 = hb[(rb + gq) * HS_STRIDE + kklo + kk + tg + 4];
                float a3 = hb[(rb + gq + 8) * HS_STRIDE + kklo + kk + tg + 4];
                unsigned af[4] = {f2tf(a0), f2tf(a1), f2tf(a2), f2tf(a3)};
                #pragma unroll
                for (int g = 0; g < 3; g++) {
                    const int wr = g * 16 + jh * 8 + gq;
                    unsigned bf[2];
                    bf[0] = Ws[wr * 1024 + ((unsigned)(kb + kk + tg) ^ swz)];
                    bf[1] = Ws[wr * 1024 + ((unsigned)(kb + kk + tg + 4) ^ swz)];
                    mma8(acc[g], af, bf);
                }
            }
            __syncthreads();                 // mma on buf (c&1) done by all

            if (c < 14) {                    // refill buf (c&1) with chunk c+2
                unsigned dst = hs_u32 + (c & 1) * (HS_BUFW * 4)
                             + prow * (HS_STRIDE * 4);
                const float* src = cur + prow * H_ + (c + 2) * 64;
                #pragma unroll
                for (int i = 0; i < 2; i++) {
                    asm volatile("cp.async.cg.shared.global [%0], [%1], 16;\n"
                                 :: "r"(dst + (pg + i) * 16), "l"(src + (pg + i) * 4));
                }
                asm volatile("cp.async.commit_group;\n");
            }
        }

        // ---- K-split reduction via smem (reuse H buffer region) ----
        float* red_s = Hs;                   // 256 x 12 floats = 12KB
        if (ks == 1) {
            int base = ((warp & 7) * 32 + lane) * 12;
            #pragma unroll
            for (int g = 0; g < 3; g++)
                #pragma unroll
                for (int i = 0; i < 4; i++) red_s[base + g * 4 + i] = acc[g][i];
        }
        __syncthreads();

        // ---- gate math (r,z,n), h update (epilogue warps) ----
        if (ks == 0) {
            int base = (warp * 32 + lane) * 12;
            #pragma unroll
            for (int g = 0; g < 3; g++)
                #pragma unroll
                for (int i = 0; i < 4; i++) acc[g][i] += red_s[base + g * 4 + i];

            #pragma unroll
            for (int i = 0; i < 4; i++) {
                int b = rb + gq + 8 * (i >> 1);
                int j = jA + (i & 1);
                float r = 1.f / (1.f + expf(-(giv[0][i] + acc[0][i] + bhv[0][i & 1])));
                float z = 1.f / (1.f + expf(-(giv[1][i] + acc[1][i] + bhv[1][i & 1])));
                float n = tanhf(giv[2][i] + r * (acc[2][i] + bhv[2][i & 1]));
                float hn = (1.f - z) * n + z * hpv[i];
                hpv[i] = hn;                 // stash for y store after arrive
                __stcg(&nxt[b * H_ + j], hn);
            }
            __threadfence();                 // release h stores
        }
        __syncthreads();                     // all fences done before arrive

        if (tid == 0) atomicAdd(&g_bar[dir], 1u);

        // y stores off the critical path (ordered by kernel boundary only)
        if (ks == 0) {
            #pragma unroll
            for (int i = 0; i < 4; i++) {
                int b = rb + gq + 8 * (i >> 1);
                int j = jA + (i & 1);
                y[(size_t)(t * B_ + b) * 2048 + dir * H_ + j] = hpv[i];
            }
        }

        if (tid == 0) {
            const unsigned target = 64u * (unsigned)(s + 1);
            while (*((volatile unsigned*)&g_bar[dir]) < target) {
                __nanosleep(32);
            }
        }
        __syncthreads();
    }
}

// ---------------- launch ------------------------------------------------------
extern "C" void kernel_launch(void* const* d_in, const int* in_sizes, int n_in,
                              void* d_out, int out_size)
{
    const float* x    = (const float*)d_in[0];
    const float* h0   = (const float*)d_in[1];
    const float* w_ih = (const float*)d_in[2];
    const float* w_hh = (const float*)d_in[3];
    const float* b_ih = (const float*)d_in[4];
    const float* b_hh = (const float*)d_in[5];
    float* out = (float*)d_out;

    cudaFuncSetAttribute(gru_persistent_kernel,
                         cudaFuncAttributeMaxDynamicSharedMemorySize,
                         SMEM_STEP);

    for (int l = 0; l < 3; l++) {
        dim3 gg(G3 / 64, TB / 128, 2);
        gemm_gi_kernel<<<gg, 256>>>(x, w_ih, b_ih, l);
        init_h_kernel<<<(2 * B_ * H_ + 255) / 256, 256>>>(h0, l);
        gru_persistent_kernel<<<128, 512, SMEM_STEP>>>(w_hh, b_hh, out, l);
    }
}

// round 7
// speedup vs baseline: 2.0372x; 1.0795x over previous
#include <cuda_runtime.h>

#define T_  256
#define B_  64
#define H_  1024
#define G3  3072
#define I_  2048
#define TB  16384   // T_*B_

// smem words: Ws[48*1024] | Hb[2][4096] | mbar[4]
#define WS_WORDS  (48 * 1024)
#define HB_WORDS  4096                       // one 64x64 f32/tf32 chunk (16KB)
#define MBAR_OFF  (WS_WORDS + 2 * HB_WORDS)
#define SMEM_STEP ((MBAR_OFF + 4) * 4)       // 229,392 B

// ---------------- scratch (static device allocations: allowed) --------------
__device__ float g_gi[2][(size_t)TB * G3];     // input projections per direction
__device__ float g_buf[2][(size_t)TB * I_];    // inter-layer activations
// h exchange: tf32 bits, blocked [chunk=k/64][b][k%64] with XOR swizzle baked in
__device__ __align__(1024) unsigned g_htf[2][2][B_ * H_];
__device__ unsigned g_bar[2];                  // per-direction step barrier

// ---------------- helpers ---------------------------------------------------
__device__ __forceinline__ unsigned f2tf(float f) {
    unsigned u;
    asm("cvt.rna.tf32.f32 %0, %1;" : "=r"(u) : "f"(f));
    return u;
}

__device__ __forceinline__ void mma8(float* c, const unsigned* a, const unsigned* b) {
    asm volatile(
        "mma.sync.aligned.m16n8k8.row.col.f32.tf32.tf32.f32 "
        "{%0,%1,%2,%3}, {%4,%5,%6,%7}, {%8,%9}, {%0,%1,%2,%3};"
        : "+f"(c[0]), "+f"(c[1]), "+f"(c[2]), "+f"(c[3])
        : "r"(a[0]), "r"(a[1]), "r"(a[2]), "r"(a[3]),
          "r"(b[0]), "r"(b[1]));
}

__device__ __forceinline__ void mbar_wait(unsigned mb, unsigned par) {
    asm volatile(
        "{\n\t.reg .pred P;\n"
        "W_%=:\n\t"
        "mbarrier.try_wait.parity.shared::cta.b64 P, [%0], %1;\n\t"
        "@!P bra W_%=;\n\t}"
        :: "r"(mb), "r"(par) : "memory");
}

// blocked+swizzled index of h[b][k] in g_htf
__device__ __forceinline__ int hidx(int b, int k) {
    return (k >> 6) * 4096 + b * 64 + ((k & 63) ^ ((b & 7) << 2));
}

// ---------------- input projection GEMM (unchanged) -------------------------
__global__ __launch_bounds__(256) void gemm_gi_kernel(
    const float* __restrict__ x, const float* __restrict__ w_ih,
    const float* __restrict__ b_ih, int l)
{
    const int d = blockIdx.z;
    const float* A    = (l == 0) ? x : g_buf[l - 1];
    const float* W    = w_ih + (size_t)(l * 2 + d) * G3 * I_;
    const float* bias = b_ih + (l * 2 + d) * G3;
    float* C = g_gi[d];

    __shared__ unsigned As[128][33];
    __shared__ unsigned Bs[64][33];

    const int tid  = threadIdx.x;
    const int lane = tid & 31, warp = tid >> 5;
    const int wm = (warp & 3) * 32, wn = (warp >> 2) * 32;
    const int m0 = blockIdx.y * 128, n0 = blockIdx.x * 64;
    const int g8 = lane >> 2, tg = lane & 3;

    float acc[2][4][4];
    #pragma unroll
    for (int a = 0; a < 2; a++)
        #pragma unroll
        for (int b = 0; b < 4; b++)
            #pragma unroll
            for (int i = 0; i < 4; i++) acc[a][b][i] = 0.f;

    for (int kt = 0; kt < I_; kt += 32) {
        #pragma unroll
        for (int i = 0; i < 4; i++) {
            int idx = tid + 256 * i;
            int row = idx >> 3, c4 = (idx & 7) * 4;
            float4 v = *reinterpret_cast<const float4*>(
                &A[(size_t)(m0 + row) * I_ + kt + c4]);
            As[row][c4]     = f2tf(v.x); As[row][c4 + 1] = f2tf(v.y);
            As[row][c4 + 2] = f2tf(v.z); As[row][c4 + 3] = f2tf(v.w);
        }
        #pragma unroll
        for (int i = 0; i < 2; i++) {
            int idx = tid + 256 * i;
            int row = idx >> 3, c4 = (idx & 7) * 4;
            float4 v = *reinterpret_cast<const float4*>(
                &W[(size_t)(n0 + row) * I_ + kt + c4]);
            Bs[row][c4]     = f2tf(v.x); Bs[row][c4 + 1] = f2tf(v.y);
            Bs[row][c4 + 2] = f2tf(v.z); Bs[row][c4 + 3] = f2tf(v.w);
        }
        __syncthreads();
        #pragma unroll
        for (int kk = 0; kk < 32; kk += 8) {
            unsigned af[2][4], bf[4][2];
            #pragma unroll
            for (int mt = 0; mt < 2; mt++) {
                int rbm = wm + mt * 16;
                af[mt][0] = As[rbm + g8][kk + tg];
                af[mt][1] = As[rbm + g8 + 8][kk + tg];
                af[mt][2] = As[rbm + g8][kk + tg + 4];
                af[mt][3] = As[rbm + g8 + 8][kk + tg + 4];
            }
            #pragma unroll
            for (int nt = 0; nt < 4; nt++) {
                int nb = wn + nt * 8 + g8;
                bf[nt][0] = Bs[nb][kk + tg];
                bf[nt][1] = Bs[nb][kk + tg + 4];
            }
            #pragma unroll
            for (int mt = 0; mt < 2; mt++)
                #pragma unroll
                for (int nt = 0; nt < 4; nt++)
                    mma8(acc[mt][nt], af[mt], bf[nt]);
        }
        __syncthreads();
    }

    #pragma unroll
    for (int mt = 0; mt < 2; mt++)
        #pragma unroll
        for (int nt = 0; nt < 4; nt++)
            #pragma unroll
            for (int i = 0; i < 4; i++) {
                int row = m0 + wm + mt * 16 + g8 + 8 * (i >> 1);
                int col = n0 + wn + nt * 8 + 2 * tg + (i & 1);
                C[(size_t)row * G3 + col] = acc[mt][nt][i] + __ldg(&bias[col]);
            }
}

// ---------------- h0 init & barrier reset -----------------------------------
__global__ void init_h_kernel(const float* __restrict__ h0, int l)
{
    int i = blockIdx.x * blockDim.x + threadIdx.x;
    if (i < 2 * B_ * H_) {
        int dir = i >> 16, rem = i & 65535;
        int b = rem >> 10, k = rem & 1023;
        float v = h0[(size_t)(2 * l + dir) * B_ * H_ + rem];
        g_htf[0][dir][hidx(b, k)] = f2tf(v);
    }
    if (i < 2) g_bar[i] = 0;
}

// ---------------- persistent recurrent kernel -------------------------------
// 128 CTAs (1/SM via 229KB smem), 512 threads / 16 warps. CTA = (dir, 16-col
// j tile); warp = (ks, jh, rb). W_hh slice resident in SMEM all 256 steps.
// h exchanged via bulk-TMA of 16KB blocked+pre-swizzled tf32 chunks; h_prev
// for own columns carried in registers across steps.
extern __shared__ unsigned smem_dyn[];

__global__ __launch_bounds__(512, 1) void gru_persistent_kernel(
    const float* __restrict__ w_hh, const float* __restrict__ b_hh,
    const float* __restrict__ h0, float* __restrict__ d_out, int l)
{
    const int cta = blockIdx.x;
    const int dir = cta >> 6;
    const int j0  = (cta & 63) * 16;
    const float* W  = w_hh + (size_t)(l * 2 + dir) * G3 * H_;
    const float* bh = b_hh + (l * 2 + dir) * G3;
    float* y = (l == 2) ? d_out : g_buf[l];

    unsigned* Ws = smem_dyn;                 // 48*1024 words, swizzled
    unsigned* Hb = smem_dyn + WS_WORDS;      // 2 x 4096-word TMA buffers
    const unsigned hb_u32 = (unsigned)__cvta_generic_to_shared(Hb);
    const unsigned mbar0  = (unsigned)__cvta_generic_to_shared(smem_dyn + MBAR_OFF);

    const int tid  = threadIdx.x;
    const int lane = tid & 31, warp = tid >> 5;
    const int ks = warp >> 3;                // K half (0,1)
    const int rb = (warp & 3) * 16;          // B rows of this warp
    const int jh = (warp >> 2) & 1;          // j half (0,1)
    const int gq = lane >> 2, tg = lane & 3;
    const unsigned swz = (unsigned)(gq << 2);
    const int kklo = ks * 32;

    // ---- load W slice once (swizzled: word = row*1024 + (col ^ ((row&7)<<2)))
    #pragma unroll 4
    for (int i = 0; i < 24; i++) {
        int idx = tid + 512 * i;
        int row = idx >> 8;                  // 0..47
        int c4  = (idx & 255) * 4;
        int g = row >> 4, jj = row & 15;
        float4 v = *reinterpret_cast<const float4*>(
            &W[(size_t)(g * H_ + j0 + jj) * H_ + c4]);
        unsigned* w = &Ws[row * 1024 + (c4 ^ ((row & 7) << 2))];
        w[0] = f2tf(v.x); w[1] = f2tf(v.y); w[2] = f2tf(v.z); w[3] = f2tf(v.w);
    }

    // ---- hoist bias & initial h_prev registers (epilogue warps only) ----
    const int jA = j0 + jh * 8 + 2 * tg;
    float bhv[3][2], hpv[4];
    if (ks == 0) {
        #pragma unroll
        for (int g = 0; g < 3; g++) {
            bhv[g][0] = __ldg(&bh[g * H_ + jA]);
            bhv[g][1] = __ldg(&bh[g * H_ + jA + 1]);
        }
        #pragma unroll
        for (int i = 0; i < 4; i++) {
            int b = rb + gq + 8 * (i >> 1);
            hpv[i] = __ldg(&h0[(size_t)(2 * l + dir) * B_ * H_
                               + (size_t)b * H_ + jA + (i & 1)]);
        }
    }

    // ---- mbarrier init ----
    if (tid == 0) {
        #pragma unroll
        for (int m = 0; m < 2; m++)
            asm volatile("mbarrier.init.shared.b64 [%0], 1;"
                         :: "r"(mbar0 + m * 8) : "memory");
        asm volatile("fence.proxy.async.shared::cta;" ::: "memory");
    }
    __syncthreads();

    for (int s = 0; s < T_; s++) {
        const int t = dir ? (T_ - 1 - s) : s;
        const unsigned* src = g_htf[s & 1][dir];
        unsigned* dstg = g_htf[(s + 1) & 1][dir];

        // ---- issue chunks 0 and 1 (TMA bulk, one thread) ----
        if (tid == 0) {
            #pragma unroll
            for (int c = 0; c < 2; c++) {
                unsigned mb = mbar0 + (c & 1) * 8;
                asm volatile("mbarrier.arrive.expect_tx.shared.b64 _, [%0], %1;"
                             :: "r"(mb), "r"(16384u) : "memory");
                asm volatile(
                    "cp.async.bulk.shared::cta.global.mbarrier::complete_tx::bytes "
                    "[%0], [%1], %2, [%3];"
                    :: "r"(hb_u32 + (c & 1) * (HB_WORDS * 4)),
                       "l"(src + c * HB_WORDS), "r"(16384u), "r"(mb)
                    : "memory");
            }
        }

        // ---- prefetch gi (epilogue warps; overlaps whole GEMM) ----
        float giv[3][4];
        if (ks == 0) {
            #pragma unroll
            for (int i = 0; i < 4; i++) {
                int b = rb + gq + 8 * (i >> 1);
                int j = jA + (i & 1);
                const float* gi = g_gi[dir] + (size_t)(t * B_ + b) * G3;
                giv[0][i] = __ldg(&gi[j]);
                giv[1][i] = __ldg(&gi[H_ + j]);
                giv[2][i] = __ldg(&gi[2 * H_ + j]);
            }
        }

        float acc[3][4];
        #pragma unroll
        for (int g = 0; g < 3; g++)
            #pragma unroll
            for (int i = 0; i < 4; i++) acc[g][i] = 0.f;

        for (int c = 0; c < 16; c++) {
            mbar_wait(mbar0 + (c & 1) * 8, (unsigned)((c >> 1) & 1));

            const unsigned* hb = Hb + (c & 1) * HB_WORDS;
            const int kb = c * 64 + kklo;    // warp's global k base in W
            #pragma unroll
            for (int kk = 0; kk < 32; kk += 8) {
                unsigned af[4];
                af[0] = hb[(rb + gq) * 64     + ((unsigned)(kklo + kk + tg)     ^ swz)];
                af[1] = hb[(rb + gq + 8) * 64 + ((unsigned)(kklo + kk + tg)     ^ swz)];
                af[2] = hb[(rb + gq) * 64     + ((unsigned)(kklo + kk + tg + 4) ^ swz)];
                af[3] = hb[(rb + gq + 8) * 64 + ((unsigned)(kklo + kk + tg + 4) ^ swz)];
                #pragma unroll
                for (int g = 0; g < 3; g++) {
                    const int wr = g * 16 + jh * 8 + gq;
                    unsigned bf[2];
                    bf[0] = Ws[wr * 1024 + ((unsigned)(kb + kk + tg) ^ swz)];
                    bf[1] = Ws[wr * 1024 + ((unsigned)(kb + kk + tg + 4) ^ swz)];
                    mma8(acc[g], af, bf);
                }
            }
            __syncthreads();                 // buffer (c&1) fully consumed

            if (c < 14 && tid == 0) {        // refill with chunk c+2
                unsigned mb = mbar0 + (c & 1) * 8;
                asm volatile("mbarrier.arrive.expect_tx.shared.b64 _, [%0], %1;"
                             :: "r"(mb), "r"(16384u) : "memory");
                asm volatile(
                    "cp.async.bulk.shared::cta.global.mbarrier::complete_tx::bytes "
                    "[%0], [%1], %2, [%3];"
                    :: "r"(hb_u32 + (c & 1) * (HB_WORDS * 4)),
                       "l"(src + (c + 2) * HB_WORDS), "r"(16384u), "r"(mb)
                    : "memory");
            }
        }

        // ---- K-split reduction via smem (reuse H buffers; all TMA drained) --
        float* red_s = reinterpret_cast<float*>(Hb);   // 256*12 floats
        if (ks == 1) {
            int base = ((warp & 7) * 32 + lane) * 12;
            #pragma unroll
            for (int g = 0; g < 3; g++)
                #pragma unroll
                for (int i = 0; i < 4; i++) red_s[base + g * 4 + i] = acc[g][i];
        }
        __syncthreads();

        // ---- gate math, h update, blocked tf32 store (epilogue warps) ----
        if (ks == 0) {
            int base = (warp * 32 + lane) * 12;
            #pragma unroll
            for (int g = 0; g < 3; g++)
                #pragma unroll
                for (int i = 0; i < 4; i++) acc[g][i] += red_s[base + g * 4 + i];

            #pragma unroll
            for (int i = 0; i < 4; i++) {
                float r = 1.f / (1.f + expf(-(giv[0][i] + acc[0][i] + bhv[0][i & 1])));
                float z = 1.f / (1.f + expf(-(giv[1][i] + acc[1][i] + bhv[1][i & 1])));
                float n = tanhf(giv[2][i] + r * (acc[2][i] + bhv[2][i & 1]));
                hpv[i] = (1.f - z) * n + z * hpv[i];
            }
            #pragma unroll
            for (int p = 0; p < 2; p++) {    // pairs (0,1),(2,3) share b
                int b = rb + gq + 8 * p;
                uint2 u = make_uint2(f2tf(hpv[2 * p]), f2tf(hpv[2 * p + 1]));
                __stcg(reinterpret_cast<uint2*>(&dstg[hidx(b, jA)]), u);
            }
            __threadfence();                 // release h stores
        }
        __syncthreads();

        if (tid == 0) atomicAdd(&g_bar[dir], 1u);

        // y stores off the critical path
        if (ks == 0) {
            #pragma unroll
            for (int i = 0; i < 4; i++) {
                int b = rb + gq + 8 * (i >> 1);
                y[(size_t)(t * B_ + b) * 2048 + dir * H_ + jA + (i & 1)] = hpv[i];
            }
        }

        if (tid == 0) {
            const unsigned target = 64u * (unsigned)(s + 1);
            while (*((volatile unsigned*)&g_bar[dir]) < target) {
                __nanosleep(32);
            }
        }
        __syncthreads();
    }
}

// ---------------- launch ------------------------------------------------------
extern "C" void kernel_launch(void* const* d_in, const int* in_sizes, int n_in,
                              void* d_out, int out_size)
{
    const float* x    = (const float*)d_in[0];
    const float* h0   = (const float*)d_in[1];
    const float* w_ih = (const float*)d_in[2];
    const float* w_hh = (const float*)d_in[3];
    const float* b_ih = (const float*)d_in[4];
    const float* b_hh = (const float*)d_in[5];
    float* out = (float*)d_out;

    cudaFuncSetAttribute(gru_persistent_kernel,
                         cudaFuncAttributeMaxDynamicSharedMemorySize,
                         SMEM_STEP);

    for (int l = 0; l < 3; l++) {
        dim3 gg(G3 / 64, TB / 128, 2);
        gemm_gi_kernel<<<gg, 256>>>(x, w_ih, b_ih, l);
        init_h_kernel<<<(2 * B_ * H_ + 255) / 256, 256>>>(h0, l);
        gru_persistent_kernel<<<128, 512, SMEM_STEP>>>(w_hh, b_hh, h0, out, l);
    }
}

// round 8
// speedup vs baseline: 3.4825x; 1.7094x over previous
#include <cuda_runtime.h>

#define T_  256
#define B_  64
#define H_  1024
#define G3  3072
#define I_  2048
#define TB  16384   // T_*B_

// smem words: Ws[48*1024] | Hb[2][4096] | mbar full[2], empty[2]
#define WS_WORDS  (48 * 1024)
#define HB_WORDS  4096                       // one 64x64 tf32 chunk (16KB)
#define MBAR_OFF  (WS_WORDS + 2 * HB_WORDS)  // word offset of barriers
#define SMEM_STEP ((MBAR_OFF + 8) * 4)       // 229,408 B

// ---------------- scratch (static device allocations: allowed) --------------
__device__ float g_gi[2][(size_t)TB * G3];     // input projections per direction
__device__ float g_buf[2][(size_t)TB * I_];    // inter-layer activations
// h exchange: tf32 bits, blocked [chunk=k/64][b][k%64], XOR swizzle baked in
__device__ __align__(1024) unsigned g_htf[2][2][B_ * H_];
__device__ unsigned g_cflag[2][16];            // per-(dir,chunk) producer counts
__device__ unsigned g_done[2];                 // per-dir lagged step counter

// ---------------- helpers ---------------------------------------------------
__device__ __forceinline__ unsigned f2tf(float f) {
    unsigned u;
    asm("cvt.rna.tf32.f32 %0, %1;" : "=r"(u) : "f"(f));
    return u;
}

__device__ __forceinline__ void mma8(float* c, const unsigned* a, const unsigned* b) {
    asm volatile(
        "mma.sync.aligned.m16n8k8.row.col.f32.tf32.tf32.f32 "
        "{%0,%1,%2,%3}, {%4,%5,%6,%7}, {%8,%9}, {%0,%1,%2,%3};"
        : "+f"(c[0]), "+f"(c[1]), "+f"(c[2]), "+f"(c[3])
        : "r"(a[0]), "r"(a[1]), "r"(a[2]), "r"(a[3]),
          "r"(b[0]), "r"(b[1]));
}

__device__ __forceinline__ void mbar_wait(unsigned mb, unsigned par) {
    asm volatile(
        "{\n\t.reg .pred P;\n"
        "W_%=:\n\t"
        "mbarrier.try_wait.parity.shared::cta.b64 P, [%0], %1;\n\t"
        "@!P bra W_%=;\n\t}"
        :: "r"(mb), "r"(par) : "memory");
}

__device__ __forceinline__ unsigned ldacq(const unsigned* p) {
    unsigned v;
    asm volatile("ld.acquire.gpu.global.u32 %0, [%1];"
                 : "=r"(v) : "l"(p) : "memory");
    return v;
}

// blocked+swizzled index of h[b][k] in g_htf
__device__ __forceinline__ int hidx(int b, int k) {
    return (k >> 6) * 4096 + b * 64 + ((k & 63) ^ ((b & 7) << 2));
}

// ---------------- input projection GEMM v2 ----------------------------------
// CTA tile 128x128, 8 warps (2m x 4n), warp tile 64x32. XOR-swizzled smem
// (conflict-free fragment loads). K chunk 32.
__global__ __launch_bounds__(256) void gemm_gi_kernel(
    const float* __restrict__ x, const float* __restrict__ w_ih,
    const float* __restrict__ b_ih, int l)
{
    const int d = blockIdx.z;
    const float* A    = (l == 0) ? x : g_buf[l - 1];
    const float* W    = w_ih + (size_t)(l * 2 + d) * G3 * I_;
    const float* bias = b_ih + (l * 2 + d) * G3;
    float* C = g_gi[d];

    __shared__ unsigned As[128 * 32];
    __shared__ unsigned Bs[128 * 32];

    const int tid  = threadIdx.x;
    const int lane = tid & 31, warp = tid >> 5;
    const int wm = (warp & 1) * 64, wn = (warp >> 1) * 32;
    const int m0 = blockIdx.y * 128, n0 = blockIdx.x * 128;
    const int g8 = lane >> 2, tg = lane & 3;
    const unsigned swz = (unsigned)(g8 << 2);

    float acc[4][4][4];
    #pragma unroll
    for (int a = 0; a < 4; a++)
        #pragma unroll
        for (int b = 0; b < 4; b++)
            #pragma unroll
            for (int i = 0; i < 4; i++) acc[a][b][i] = 0.f;

    for (int kt = 0; kt < I_; kt += 32) {
        #pragma unroll
        for (int i = 0; i < 4; i++) {            // A tile 128x32
            int idx = tid + 256 * i;
            int row = idx >> 3, c4 = (idx & 7) * 4;
            float4 v = *reinterpret_cast<const float4*>(
                &A[(size_t)(m0 + row) * I_ + kt + c4]);
            unsigned* p = &As[row * 32 + (c4 ^ ((row & 7) << 2))];
            p[0] = f2tf(v.x); p[1] = f2tf(v.y); p[2] = f2tf(v.z); p[3] = f2tf(v.w);
        }
        #pragma unroll
        for (int i = 0; i < 4; i++) {            // B tile 128x32 (W rows)
            int idx = tid + 256 * i;
            int row = idx >> 3, c4 = (idx & 7) * 4;
            float4 v = *reinterpret_cast<const float4*>(
                &W[(size_t)(n0 + row) * I_ + kt + c4]);
            unsigned* p = &Bs[row * 32 + (c4 ^ ((row & 7) << 2))];
            p[0] = f2tf(v.x); p[1] = f2tf(v.y); p[2] = f2tf(v.z); p[3] = f2tf(v.w);
        }
        __syncthreads();
        #pragma unroll
        for (int kk = 0; kk < 32; kk += 8) {
            unsigned af[4][4], bf[4][2];
            #pragma unroll
            for (int mt = 0; mt < 4; mt++) {
                int r = wm + mt * 16 + g8;
                af[mt][0] = As[r * 32 + ((unsigned)(kk + tg) ^ swz)];
                af[mt][1] = As[(r + 8) * 32 + ((unsigned)(kk + tg) ^ swz)];
                af[mt][2] = As[r * 32 + ((unsigned)(kk + tg + 4) ^ swz)];
                af[mt][3] = As[(r + 8) * 32 + ((unsigned)(kk + tg + 4) ^ swz)];
            }
            #pragma unroll
            for (int nt = 0; nt < 4; nt++) {
                int r = wn + nt * 8 + g8;
                bf[nt][0] = Bs[r * 32 + ((unsigned)(kk + tg) ^ swz)];
                bf[nt][1] = Bs[r * 32 + ((unsigned)(kk + tg + 4) ^ swz)];
            }
            #pragma unroll
            for (int mt = 0; mt < 4; mt++)
                #pragma unroll
                for (int nt = 0; nt < 4; nt++)
                    mma8(acc[mt][nt], af[mt], bf[nt]);
        }
        __syncthreads();
    }

    #pragma unroll
    for (int mt = 0; mt < 4; mt++)
        #pragma unroll
        for (int nt = 0; nt < 4; nt++)
            #pragma unroll
            for (int i = 0; i < 4; i++) {
                int row = m0 + wm + mt * 16 + g8 + 8 * (i >> 1);
                int col = n0 + wn + nt * 8 + 2 * tg + (i & 1);
                C[(size_t)row * G3 + col] = acc[mt][nt][i] + __ldg(&bias[col]);
            }
}

// ---------------- h0 init & flag reset --------------------------------------
__global__ void init_h_kernel(const float* __restrict__ h0, int l)
{
    int i = blockIdx.x * blockDim.x + threadIdx.x;
    if (i < 2 * B_ * H_) {
        int dir = i >> 16, rem = i & 65535;
        int b = rem >> 10, k = rem & 1023;
        float v = h0[(size_t)(2 * l + dir) * B_ * H_ + rem];
        g_htf[0][dir][hidx(b, k)] = f2tf(v);
    }
    if (i < 32) g_cflag[i >> 4][i & 15] = 4u;   // h0 counts as step-0 data
    if (i < 2)  g_done[i] = 0u;
}

// ---------------- persistent recurrent kernel -------------------------------
// 128 CTAs (1/SM, 229KB smem), 544 threads: 16 compute warps (ks,jh,rb) +
// 1 control warp. No per-step hard barrier: control warp pipelines TMA chunk
// loads gated on per-chunk producer flags; buffer reuse via full/empty
// mbarriers; write-after-read safety via lagged g_done counter.
extern __shared__ unsigned smem_dyn[];

__global__ __launch_bounds__(544, 1) void gru_persistent_kernel(
    const float* __restrict__ w_hh, const float* __restrict__ b_hh,
    const float* __restrict__ h0, float* __restrict__ d_out, int l)
{
    const int cta = blockIdx.x;
    const int dir = cta >> 6;
    const int j0  = (cta & 63) * 16;
    const int cj  = (cta & 63) >> 2;         // chunk this CTA produces
    const float* W  = w_hh + (size_t)(l * 2 + dir) * G3 * H_;
    const float* bh = b_hh + (l * 2 + dir) * G3;
    float* y = (l == 2) ? d_out : g_buf[l];

    unsigned* Ws = smem_dyn;                 // 48*1024 words, swizzled
    unsigned* Hb = smem_dyn + WS_WORDS;      // 2 x 4096-word TMA buffers
    const unsigned hb_u32 = (unsigned)__cvta_generic_to_shared(Hb);
    const unsigned mb_full  = (unsigned)__cvta_generic_to_shared(smem_dyn + MBAR_OFF);
    const unsigned mb_empty = mb_full + 16;

    const int tid  = threadIdx.x;
    const int lane = tid & 31, warp = tid >> 5;
    const int ks = warp >> 3;                // 0,1 compute K halves; 2 = control
    const int rb = (warp & 3) * 16;
    const int jh = (warp >> 2) & 1;
    const int gq = lane >> 2, tg = lane & 3;
    const unsigned swz = (unsigned)(gq << 2);
    const int kklo = (ks & 1) * 32;

    // ---- load W slice once (compute warps only) ----
    if (tid < 512) {
        #pragma unroll 4
        for (int i = 0; i < 24; i++) {
            int idx = tid + 512 * i;
            int row = idx >> 8;              // 0..47
            int c4  = (idx & 255) * 4;
            int g = row >> 4, jj = row & 15;
            float4 v = *reinterpret_cast<const float4*>(
                &W[(size_t)(g * H_ + j0 + jj) * H_ + c4]);
            unsigned* w = &Ws[row * 1024 + (c4 ^ ((row & 7) << 2))];
            w[0] = f2tf(v.x); w[1] = f2tf(v.y); w[2] = f2tf(v.z); w[3] = f2tf(v.w);
        }
    }

    // ---- bias & initial h_prev registers (epilogue warps) ----
    const int jA = j0 + jh * 8 + 2 * tg;
    float bhv[3][2], hpv[4];
    if (ks == 0) {
        #pragma unroll
        for (int g = 0; g < 3; g++) {
            bhv[g][0] = __ldg(&bh[g * H_ + jA]);
            bhv[g][1] = __ldg(&bh[g * H_ + jA + 1]);
        }
        #pragma unroll
        for (int i = 0; i < 4; i++) {
            int b = rb + gq + 8 * (i >> 1);
            hpv[i] = __ldg(&h0[(size_t)(2 * l + dir) * B_ * H_
                               + (size_t)b * H_ + jA + (i & 1)]);
        }
    }

    // ---- mbarrier init: full count 1 (expect_tx), empty count 16 ----
    if (tid == 0) {
        #pragma unroll
        for (int m = 0; m < 2; m++) {
            asm volatile("mbarrier.init.shared.b64 [%0], 1;"
                         :: "r"(mb_full + m * 8) : "memory");
            asm volatile("mbarrier.init.shared.b64 [%0], 16;"
                         :: "r"(mb_empty + m * 8) : "memory");
        }
        asm volatile("fence.proxy.async.shared::cta;" ::: "memory");
    }
    __syncthreads();

    unsigned fuse[2] = {0, 0};               // compute: full-phase counters
    unsigned euse[2] = {0, 0};               // control: slot use counters

    for (int s = 0; s < T_; s++) {
        const int t = dir ? (T_ - 1 - s) : s;
        const unsigned* src = g_htf[s & 1][dir];
        unsigned* dstg = g_htf[(s + 1) & 1][dir];

        if (warp == 16) {
            // ---------------- control warp: issue all 16 chunk TMAs --------
            if (lane == 0) {
                const unsigned tgt = 4u * (unsigned)(s + 1);
                for (int c = 0; c < 16; c++) {
                    int slot = c & 1;
                    if (euse[slot] > 0)
                        mbar_wait(mb_empty + slot * 8, (euse[slot] - 1) & 1);
                    euse[slot]++;
                    while (ldacq(&g_cflag[dir][c]) < tgt) __nanosleep(20);
                    unsigned mb = mb_full + slot * 8;
                    asm volatile("mbarrier.arrive.expect_tx.shared.b64 _, [%0], %1;"
                                 :: "r"(mb), "r"(16384u) : "memory");
                    asm volatile(
                        "cp.async.bulk.shared::cta.global.mbarrier::complete_tx::bytes "
                        "[%0], [%1], %2, [%3];"
                        :: "r"(hb_u32 + slot * (HB_WORDS * 4)),
                           "l"(src + c * HB_WORDS), "r"(16384u), "r"(mb)
                        : "memory");
                }
            } else {
                // non-leader control lanes: keep euse in sync (no waits)
                euse[0] += 8; euse[1] += 8;
            }
        }

        float acc[3][4];
        #pragma unroll
        for (int g = 0; g < 3; g++)
            #pragma unroll
            for (int i = 0; i < 4; i++) acc[g][i] = 0.f;

        float giv[3][4];
        if (ks == 0) {                       // gi prefetch overlaps GEMM
            #pragma unroll
            for (int i = 0; i < 4; i++) {
                int b = rb + gq + 8 * (i >> 1);
                int j = jA + (i & 1);
                const float* gi = g_gi[dir] + (size_t)(t * B_ + b) * G3;
                giv[0][i] = __ldg(&gi[j]);
                giv[1][i] = __ldg(&gi[H_ + j]);
                giv[2][i] = __ldg(&gi[2 * H_ + j]);
            }
        }

        if (warp < 16) {
            // ---------------- compute warps: consume 16 chunks -------------
            for (int c = 0; c < 16; c++) {
                int slot = c & 1;
                mbar_wait(mb_full + slot * 8, fuse[slot] & 1);
                fuse[slot]++;

                const unsigned* hb = Hb + slot * HB_WORDS;
                const int kb = c * 64 + kklo;
                #pragma unroll
                for (int kk = 0; kk < 32; kk += 8) {
                    unsigned af[4];
                    af[0] = hb[(rb + gq) * 64     + ((unsigned)(kklo + kk + tg)     ^ swz)];
                    af[1] = hb[(rb + gq + 8) * 64 + ((unsigned)(kklo + kk + tg)     ^ swz)];
                    af[2] = hb[(rb + gq) * 64     + ((unsigned)(kklo + kk + tg + 4) ^ swz)];
                    af[3] = hb[(rb + gq + 8) * 64 + ((unsigned)(kklo + kk + tg + 4) ^ swz)];
                    #pragma unroll
                    for (int g = 0; g < 3; g++) {
                        const int wr = g * 16 + jh * 8 + gq;
                        unsigned bf[2];
                        bf[0] = Ws[wr * 1024 + ((unsigned)(kb + kk + tg) ^ swz)];
                        bf[1] = Ws[wr * 1024 + ((unsigned)(kb + kk + tg + 4) ^ swz)];
                        mma8(acc[g], af, bf);
                    }
                }
                if (lane == 0)
                    asm volatile("mbarrier.arrive.shared.b64 _, [%0];"
                                 :: "r"(mb_empty + slot * 8) : "memory");
            }
        }

        __syncthreads();                     // sync1: all chunks consumed

        // ---- K-split partials into Hb slot 0 (free: control gated below) --
        float* red_s = reinterpret_cast<float*>(Hb);
        if (ks == 1) {
            int base = ((warp & 7) * 32 + lane) * 12;
            #pragma unroll
            for (int g = 0; g < 3; g++)
                #pragma unroll
                for (int i = 0; i < 4; i++) red_s[base + g * 4 + i] = acc[g][i];
        }
        if (tid == 0 && s > 0) {             // lagged write-gate (usually free)
            const unsigned tgt = 64u * (unsigned)s;
            while (ldacq(&g_done[dir]) < tgt) __nanosleep(20);
        }
        __syncthreads();                     // sync2

        if (ks == 0) {
            int base = (warp * 32 + lane) * 12;
            #pragma unroll
            for (int g = 0; g < 3; g++)
                #pragma unroll
                for (int i = 0; i < 4; i++) acc[g][i] += red_s[base + g * 4 + i];

            #pragma unroll
            for (int i = 0; i < 4; i++) {
                float r = 1.f / (1.f + expf(-(giv[0][i] + acc[0][i] + bhv[0][i & 1])));
                float z = 1.f / (1.f + expf(-(giv[1][i] + acc[1][i] + bhv[1][i & 1])));
                float n = tanhf(giv[2][i] + r * (acc[2][i] + bhv[2][i & 1]));
                hpv[i] = (1.f - z) * n + z * hpv[i];
            }
            #pragma unroll
            for (int p = 0; p < 2; p++) {
                int b = rb + gq + 8 * p;
                uint2 u = make_uint2(f2tf(hpv[2 * p]), f2tf(hpv[2 * p + 1]));
                __stcg(reinterpret_cast<uint2*>(&dstg[hidx(b, jA)]), u);
            }
        }
        __syncthreads();                     // sync3: h stores done CTA-wide

        if (tid == 0) {
            __threadfence();                 // cumulative release of h stores
            atomicAdd(&g_cflag[dir][cj], 1u);
            atomicAdd(&g_done[dir], 1u);
        }
        if (ks == 0) {                       // y stores off the critical path
            #pragma unroll
            for (int i = 0; i < 4; i++) {
                int b = rb + gq + 8 * (i >> 1);
                y[(size_t)(t * B_ + b) * 2048 + dir * H_ + jA + (i & 1)] = hpv[i];
            }
        }
    }
}

// ---------------- launch ------------------------------------------------------
extern "C" void kernel_launch(void* const* d_in, const int* in_sizes, int n_in,
                              void* d_out, int out_size)
{
    const float* x    = (const float*)d_in[0];
    const float* h0   = (const float*)d_in[1];
    const float* w_ih = (const float*)d_in[2];
    const float* w_hh = (const float*)d_in[3];
    const float* b_ih = (const float*)d_in[4];
    const float* b_hh = (const float*)d_in[5];
    float* out = (float*)d_out;

    cudaFuncSetAttribute(gru_persistent_kernel,
                         cudaFuncAttributeMaxDynamicSharedMemorySize,
                         SMEM_STEP);

    for (int l = 0; l < 3; l++) {
        dim3 gg(G3 / 128, TB / 128, 2);
        gemm_gi_kernel<<<gg, 256>>>(x, w_ih, b_ih, l);
        init_h_kernel<<<(2 * B_ * H_ + 255) / 256, 256>>>(h0, l);
        gru_persistent_kernel<<<128, 544, SMEM_STEP>>>(w_hh, b_hh, h0, out, l);
    }
}